// round 6
// baseline (speedup 1.0000x reference)
#include <cuda_runtime.h>
#include <cstdint>
#include <math.h>

#define S_FIX 16384

// ---------------- scratch (device globals; no allocations allowed) ----------
__device__ __align__(128) int   d_start[S_FIX + 1];
__device__ __align__(128) float d_mean[(size_t)S_FIX * 256];      // 16 MB
__device__ __align__(128) float d_G[(size_t)S_FIX * 2048];        // 134 MB  G[s, d*8+h]
__device__ __align__(128) float d_A[(size_t)S_FIX * 2048];        // 134 MB  A[s, d*8+h]
__device__ __align__(128) float d_Bbig[256 * 2048];               // Bbig[e, d*8+h]
__device__ __align__(128) float d_Mstack[2048 * 256];             // Mstack[d*8+h, j]

// ---------------- segment bounds via binary search (map is sorted) ----------
__global__ __launch_bounds__(256) void k_bounds(const int* __restrict__ seg, int N, int S) {
    int s = blockIdx.x * 256 + threadIdx.x;
    if (s > S) return;
    int lo = 0, hi = N;
    while (lo < hi) {
        int mid = (lo + hi) >> 1;
        if (seg[mid] < s) lo = mid + 1; else hi = mid;
    }
    d_start[s] = lo;
}

// ---------------- precompute Bbig and Mstack (tiny) -------------------------
__global__ __launch_bounds__(256) void k_prep(const float* __restrict__ Wq,
                                              const float* __restrict__ Wk,
                                              const float* __restrict__ Wv,
                                              const float* __restrict__ Wo) {
    int idx = blockIdx.x * 256 + threadIdx.x;   // 0 .. 524287
    {
        int e = idx >> 11, r = idx & 2047, d = r >> 3, h = r & 7;
        const float* wq = Wq + e * 256 + h * 32;
        const float* wk = Wk + d * 256 + h * 32;
        float s = 0.f;
        #pragma unroll
        for (int j = 0; j < 32; j++) s += wq[j] * wk[j];
        d_Bbig[idx] = s;
    }
    {
        int j = idx & 255, c = idx >> 8, d = c >> 3, h = c & 7;
        const float* wv = Wv + d * 256 + h * 32;
        const float* wo = Wo + (h * 32) * 256 + j;
        float s = 0.f;
        #pragma unroll
        for (int t = 0; t < 32; t++) s += wv[t] * wo[t * 256];
        d_Mstack[idx] = s;
    }
}

// ---------------- segment mean pool (one 512MB x pass) ----------------------
__global__ __launch_bounds__(256) void k_pool(const float* __restrict__ x) {
    int s = blockIdx.x, d = threadIdx.x;
    int b = d_start[s], e = d_start[s + 1];
    float acc = 0.f;
    for (int n = b; n < e; n++) acc += x[(size_t)n * 256 + d];
    int c = e - b; if (c < 1) c = 1;
    d_mean[(size_t)s * 256 + d] = acc / (float)c;
}

// ---------------- tf32 mma GEMM: C[M,N] = A[M,K] @ B[K,N], row-major --------
__device__ __forceinline__ uint32_t f2tf(float f) {
    uint32_t r;
    asm("cvt.rna.tf32.f32 %0, %1;" : "=r"(r) : "f"(f));
    return r;
}
__device__ __forceinline__ void mma_tf32(float* c, const uint32_t* a, const uint32_t* b) {
    asm volatile("mma.sync.aligned.m16n8k8.row.col.f32.tf32.tf32.f32 "
                 "{%0,%1,%2,%3},{%4,%5,%6,%7},{%8,%9},{%0,%1,%2,%3};\n"
                 : "+f"(c[0]), "+f"(c[1]), "+f"(c[2]), "+f"(c[3])
                 : "r"(a[0]), "r"(a[1]), "r"(a[2]), "r"(a[3]), "r"(b[0]), "r"(b[1]));
}

struct Stage { float4 a[4]; float4 b[4]; };

__device__ __forceinline__ void load_stage(Stage& st, const float* __restrict__ A,
                                           const float* __restrict__ B,
                                           long bm, long bn, int K, int N, int kt, int tid) {
    #pragma unroll
    for (int it = 0; it < 4; it++) {
        int idx = tid + it * 256; int r = idx >> 3, c = idx & 7;
        st.a[it] = *(const float4*)(A + (bm + r) * (long)K + kt * 32 + c * 4);
    }
    #pragma unroll
    for (int it = 0; it < 4; it++) {
        int idx = tid + it * 256; int r = idx >> 5, c = idx & 31;
        st.b[it] = *(const float4*)(B + ((long)kt * 32 + r) * (long)N + bn + c * 4);
    }
}

__global__ __launch_bounds__(256) void k_gemm(int mode, float* __restrict__ Cout,
                                              int M, int N, int K) {
    const float* A = mode ? d_A : d_mean;
    const float* B = mode ? d_Mstack : d_Bbig;
    float* C = mode ? Cout : d_G;

    __shared__ __align__(16) uint32_t As[128 * 36];
    __shared__ __align__(16) uint32_t Bs[32 * 136];

    int tid = threadIdx.x, lane = tid & 31, wid = tid >> 5;
    int wm = wid & 1, wn = wid >> 1;                  // 2 x 4 warp grid, warp tile 64x32
    long bm = (long)blockIdx.y * 128, bn = (long)blockIdx.x * 128;

    float acc[4][4][4];
    #pragma unroll
    for (int i = 0; i < 4; i++)
        #pragma unroll
        for (int j = 0; j < 4; j++)
            #pragma unroll
            for (int q = 0; q < 4; q++) acc[i][j][q] = 0.f;

    int nk = K >> 5;
    Stage st;
    load_stage(st, A, B, bm, bn, K, N, 0, tid);

    for (int kt = 0; kt < nk; kt++) {
        __syncthreads();
        #pragma unroll
        for (int it = 0; it < 4; it++) {
            int idx = tid + it * 256; int r = idx >> 3, c = idx & 7;
            uint4 v = make_uint4(f2tf(st.a[it].x), f2tf(st.a[it].y), f2tf(st.a[it].z), f2tf(st.a[it].w));
            *(uint4*)&As[r * 36 + c * 4] = v;
        }
        #pragma unroll
        for (int it = 0; it < 4; it++) {
            int idx = tid + it * 256; int r = idx >> 5, c = idx & 31;
            uint4 v = make_uint4(f2tf(st.b[it].x), f2tf(st.b[it].y), f2tf(st.b[it].z), f2tf(st.b[it].w));
            *(uint4*)&Bs[r * 136 + c * 4] = v;
        }
        __syncthreads();
        if (kt + 1 < nk) load_stage(st, A, B, bm, bn, K, N, kt + 1, tid);

        #pragma unroll
        for (int kk = 0; kk < 32; kk += 8) {
            uint32_t af[4][4], bf[4][2];
            #pragma unroll
            for (int fm = 0; fm < 4; fm++) {
                int row = wm * 64 + fm * 16 + (lane >> 2);
                int col = kk + (lane & 3);
                af[fm][0] = As[row * 36 + col];
                af[fm][1] = As[(row + 8) * 36 + col];
                af[fm][2] = As[row * 36 + col + 4];
                af[fm][3] = As[(row + 8) * 36 + col + 4];
            }
            #pragma unroll
            for (int fn = 0; fn < 4; fn++) {
                int cn = wn * 32 + fn * 8 + (lane >> 2);
                int rk = kk + (lane & 3);
                bf[fn][0] = Bs[rk * 136 + cn];
                bf[fn][1] = Bs[(rk + 4) * 136 + cn];
            }
            #pragma unroll
            for (int fm = 0; fm < 4; fm++)
                #pragma unroll
                for (int fn = 0; fn < 4; fn++)
                    mma_tf32(acc[fm][fn], af[fm], bf[fn]);
        }
    }

    #pragma unroll
    for (int fm = 0; fm < 4; fm++) {
        long row = bm + wm * 64 + fm * 16 + (lane >> 2);
        #pragma unroll
        for (int fn = 0; fn < 4; fn++) {
            long col = bn + wn * 32 + fn * 8 + (lane & 3) * 2;
            *(float2*)&C[row * N + col]       = make_float2(acc[fm][fn][0], acc[fm][fn][1]);
            *(float2*)&C[(row + 8) * N + col] = make_float2(acc[fm][fn][2], acc[fm][fn][3]);
        }
    }
}

// ---------------- fused scores + online softmax + A accumulation ------------
// One block per segment. x chunk cached in smem; single pass over x (512 MB).
__global__ __launch_bounds__(256) void k_fused(const float* __restrict__ x) {
    __shared__ __align__(16) float g_sh[2048];        // G row for this segment
    __shared__ __align__(16) float x_sh[32 * 256];    // chunk of x rows
    __shared__ __align__(16) float sc_sh[32 * 8];     // per-row per-head exp weights
    __shared__ float f_sh[8];                         // rescale factors
    __shared__ float den_sh[8];

    int s = blockIdx.x;
    int tid = threadIdx.x, lane = tid & 31, w = tid >> 5;
    int b = d_start[s], e = d_start[s + 1];

    // load G row (2048 floats)
    {
        const float4* gp = (const float4*)(d_G + (size_t)s * 2048);
        float4* gs = (float4*)g_sh;
        gs[tid] = gp[tid];
        gs[tid + 256] = gp[tid + 256];
    }

    float a0 = 0, a1 = 0, a2 = 0, a3 = 0, a4 = 0, a5 = 0, a6 = 0, a7 = 0; // A[d=tid, h]
    float m_run = -3.4e38f, den_run = 0.f;            // per-warp (warp w = head w)
    const float scale = 0.17677669529663687f;         // 1/sqrt(32)

    for (int c0 = b; c0 < e; c0 += 32) {
        int m = min(32, e - c0);
        __syncthreads();  // prior reads of x_sh / sc_sh done
        // cooperative chunk load (float4, coalesced)
        {
            const float4* xg = (const float4*)(x + (size_t)c0 * 256);
            float4* xs = (float4*)x_sh;
            for (int i = tid; i < m * 64; i += 256) xs[i] = xg[i];
        }
        __syncthreads();

        // scores: warp w takes rows i = w, w+8, ...
        for (int i = w; i < m; i += 8) {
            const float* xr = x_sh + i * 256;
            float p0 = 0, p1 = 0, p2 = 0, p3 = 0, p4 = 0, p5 = 0, p6 = 0, p7 = 0;
            #pragma unroll
            for (int dd = 0; dd < 8; dd++) {
                int d = lane + dd * 32;
                float xv = xr[d];
                float4 g0 = *(const float4*)&g_sh[d * 8];
                float4 g1 = *(const float4*)&g_sh[d * 8 + 4];
                p0 += xv * g0.x; p1 += xv * g0.y; p2 += xv * g0.z; p3 += xv * g0.w;
                p4 += xv * g1.x; p5 += xv * g1.y; p6 += xv * g1.z; p7 += xv * g1.w;
            }
            #pragma unroll
            for (int off = 16; off; off >>= 1) {
                p0 += __shfl_xor_sync(0xffffffffu, p0, off);
                p1 += __shfl_xor_sync(0xffffffffu, p1, off);
                p2 += __shfl_xor_sync(0xffffffffu, p2, off);
                p3 += __shfl_xor_sync(0xffffffffu, p3, off);
                p4 += __shfl_xor_sync(0xffffffffu, p4, off);
                p5 += __shfl_xor_sync(0xffffffffu, p5, off);
                p6 += __shfl_xor_sync(0xffffffffu, p6, off);
                p7 += __shfl_xor_sync(0xffffffffu, p7, off);
            }
            if (lane == 0) {
                *(float4*)&sc_sh[i * 8]     = make_float4(p0 * scale, p1 * scale, p2 * scale, p3 * scale);
                *(float4*)&sc_sh[i * 8 + 4] = make_float4(p4 * scale, p5 * scale, p6 * scale, p7 * scale);
            }
        }
        __syncthreads();

        // online softmax update: warp w owns head w
        {
            float sc = (lane < m) ? sc_sh[lane * 8 + w] : -3.4e38f;
            float cmax = sc;
            #pragma unroll
            for (int off = 16; off; off >>= 1)
                cmax = fmaxf(cmax, __shfl_xor_sync(0xffffffffu, cmax, off));
            float nm = fmaxf(m_run, cmax);
            float f = __expf(m_run - nm);
            float ev = (lane < m) ? __expf(sc - nm) : 0.f;
            if (lane < m) sc_sh[lane * 8 + w] = ev;
            float csum = ev;
            #pragma unroll
            for (int off = 16; off; off >>= 1)
                csum += __shfl_xor_sync(0xffffffffu, csum, off);
            den_run = den_run * f + csum;
            m_run = nm;
            if (lane == 0) f_sh[w] = f;
        }
        __syncthreads();

        // accumulate A: thread tid owns d = tid, all 8 heads
        {
            float f0 = f_sh[0], f1 = f_sh[1], f2 = f_sh[2], f3 = f_sh[3];
            float f4 = f_sh[4], f5 = f_sh[5], f6 = f_sh[6], f7 = f_sh[7];
            a0 *= f0; a1 *= f1; a2 *= f2; a3 *= f3;
            a4 *= f4; a5 *= f5; a6 *= f6; a7 *= f7;
            for (int i = 0; i < m; i++) {
                float xv = x_sh[i * 256 + tid];
                float4 e0 = *(const float4*)&sc_sh[i * 8];
                float4 e1 = *(const float4*)&sc_sh[i * 8 + 4];
                a0 += e0.x * xv; a1 += e0.y * xv; a2 += e0.z * xv; a3 += e0.w * xv;
                a4 += e1.x * xv; a5 += e1.y * xv; a6 += e1.z * xv; a7 += e1.w * xv;
            }
        }
    }

    // publish denominators
    if (lane == 0) den_sh[w] = den_run;
    __syncthreads();

    float r0 = den_sh[0] > 0.f ? 1.f / den_sh[0] : 0.f;
    float r1 = den_sh[1] > 0.f ? 1.f / den_sh[1] : 0.f;
    float r2 = den_sh[2] > 0.f ? 1.f / den_sh[2] : 0.f;
    float r3 = den_sh[3] > 0.f ? 1.f / den_sh[3] : 0.f;
    float r4 = den_sh[4] > 0.f ? 1.f / den_sh[4] : 0.f;
    float r5 = den_sh[5] > 0.f ? 1.f / den_sh[5] : 0.f;
    float r6 = den_sh[6] > 0.f ? 1.f / den_sh[6] : 0.f;
    float r7 = den_sh[7] > 0.f ? 1.f / den_sh[7] : 0.f;

    float* ap = d_A + (size_t)s * 2048 + tid * 8;
    *(float4*)ap       = make_float4(a0 * r0, a1 * r1, a2 * r2, a3 * r3);
    *(float4*)(ap + 4) = make_float4(a4 * r4, a5 * r5, a6 * r6, a7 * r7);
}

// ---------------- launch ----------------------------------------------------
extern "C" void kernel_launch(void* const* d_in, const int* in_sizes, int n_in,
                              void* d_out, int out_size) {
    const float* x   = (const float*)d_in[0];
    const int*   seg = (const int*)d_in[1];
    int wb = n_in - 4;                      // weights are the last 4 inputs
    const float* Wq = (const float*)d_in[wb + 0];
    const float* Wk = (const float*)d_in[wb + 1];
    const float* Wv = (const float*)d_in[wb + 2];
    const float* Wo = (const float*)d_in[wb + 3];
    float* out = (float*)d_out;

    int N = in_sizes[0] / 256;
    const int S = S_FIX;

    k_bounds<<<(S + 1 + 255) / 256, 256>>>(seg, N, S);
    k_prep<<<2048, 256>>>(Wq, Wk, Wv, Wo);
    k_pool<<<S, 256>>>(x);
    k_gemm<<<dim3(2048 / 128, S / 128), 256>>>(0, nullptr, S, 2048, 256);   // G = mean @ Bbig
    k_fused<<<S, 256>>>(x);
    k_gemm<<<dim3(256 / 128, S / 128), 256>>>(1, out, S, 256, 2048);        // out = A @ Mstack
}

// round 11
// speedup vs baseline: 1.0656x; 1.0656x over previous
#include <cuda_runtime.h>
#include <cstdint>
#include <math.h>

#define S_FIX 16384

// ---------------- scratch (device globals; no allocations allowed) ----------
__device__ __align__(128) int   d_start[S_FIX + 1];
__device__ __align__(128) float d_mean[(size_t)S_FIX * 256];      // 16 MB  (tf32-rounded)
__device__ __align__(128) float d_G[(size_t)S_FIX * 2048];        // 134 MB G[s, d*8+h]
__device__ __align__(128) float d_A[(size_t)S_FIX * 2048];        // 134 MB A[s, d*8+h] (tf32-rounded)
__device__ __align__(128) float d_Bbig[256 * 2048];               // tf32-rounded
__device__ __align__(128) float d_Mstack[2048 * 256];             // tf32-rounded

__device__ __forceinline__ uint32_t f2tf(float f) {
    uint32_t r;
    asm("cvt.rna.tf32.f32 %0, %1;" : "=r"(r) : "f"(f));
    return r;
}
__device__ __forceinline__ float tfround(float f) { return __uint_as_float(f2tf(f)); }

// ---------------- segment bounds via binary search (map is sorted) ----------
__global__ __launch_bounds__(256) void k_bounds(const int* __restrict__ seg, int N, int S) {
    int s = blockIdx.x * 256 + threadIdx.x;
    if (s > S) return;
    int lo = 0, hi = N;
    while (lo < hi) {
        int mid = (lo + hi) >> 1;
        if (seg[mid] < s) lo = mid + 1; else hi = mid;
    }
    d_start[s] = lo;
}

// ---------------- precompute Bbig and Mstack (tiny; tf32-rounded) -----------
__global__ __launch_bounds__(256) void k_prep(const float* __restrict__ Wq,
                                              const float* __restrict__ Wk,
                                              const float* __restrict__ Wv,
                                              const float* __restrict__ Wo) {
    int idx = blockIdx.x * 256 + threadIdx.x;   // 0 .. 524287
    {
        int e = idx >> 11, r = idx & 2047, d = r >> 3, h = r & 7;
        const float* wq = Wq + e * 256 + h * 32;
        const float* wk = Wk + d * 256 + h * 32;
        float s = 0.f;
        #pragma unroll
        for (int j = 0; j < 32; j++) s += wq[j] * wk[j];
        d_Bbig[idx] = tfround(s);
    }
    {
        int j = idx & 255, c = idx >> 8, d = c >> 3, h = c & 7;
        const float* wv = Wv + d * 256 + h * 32;
        const float* wo = Wo + (h * 32) * 256 + j;
        float s = 0.f;
        #pragma unroll
        for (int t = 0; t < 32; t++) s += wv[t] * wo[t * 256];
        d_Mstack[idx] = tfround(s);
    }
}

// ---------------- segment mean pool (one 512MB x pass, MLP=4) ---------------
__global__ __launch_bounds__(256) void k_pool(const float* __restrict__ x) {
    int s = blockIdx.x, d = threadIdx.x;
    int b = d_start[s], e = d_start[s + 1];
    float a0 = 0.f, a1 = 0.f, a2 = 0.f, a3 = 0.f;
    int n = b;
    for (; n + 4 <= e; n += 4) {
        a0 += x[(size_t)n * 256 + d];
        a1 += x[(size_t)(n + 1) * 256 + d];
        a2 += x[(size_t)(n + 2) * 256 + d];
        a3 += x[(size_t)(n + 3) * 256 + d];
    }
    for (; n < e; n++) a0 += x[(size_t)n * 256 + d];
    float acc = (a0 + a1) + (a2 + a3);
    int c = e - b; if (c < 1) c = 1;
    d_mean[(size_t)s * 256 + d] = tfround(acc / (float)c);
}

// ---------------- tf32 mma GEMM, cp.async double-buffered -------------------
// C[M,N] = A[M,K] @ B[K,N], row-major. Operands are pre-rounded tf32 values.
__device__ __forceinline__ void mma_tf32(float* c, const uint32_t* a, const uint32_t* b) {
    asm volatile("mma.sync.aligned.m16n8k8.row.col.f32.tf32.tf32.f32 "
                 "{%0,%1,%2,%3},{%4,%5,%6,%7},{%8,%9},{%0,%1,%2,%3};\n"
                 : "+f"(c[0]), "+f"(c[1]), "+f"(c[2]), "+f"(c[3])
                 : "r"(a[0]), "r"(a[1]), "r"(a[2]), "r"(a[3]), "r"(b[0]), "r"(b[1]));
}
__device__ __forceinline__ void cpasync16(float* smem, const float* gmem) {
    uint32_t s = (uint32_t)__cvta_generic_to_shared(smem);
    asm volatile("cp.async.cg.shared.global [%0], [%1], 16;\n" :: "r"(s), "l"(gmem));
}

#define AS_STRIDE 36
#define BS_STRIDE 136
#define AS_BUF (128 * AS_STRIDE)    // 4608 floats
#define BS_BUF (32 * BS_STRIDE)     // 4352 floats
#define GEMM_SMEM ((2 * (AS_BUF + BS_BUF)) * 4)   // 71680 bytes

__global__ __launch_bounds__(256, 2) void k_gemm(int mode, float* __restrict__ Cout,
                                                 int M, int N, int K) {
    const float* Ag = mode ? d_A : d_mean;
    const float* Bg = mode ? d_Mstack : d_Bbig;
    float* C = mode ? Cout : d_G;

    extern __shared__ float sm[];
    float* As = sm;                   // [2][AS_BUF]
    float* Bs = sm + 2 * AS_BUF;      // [2][BS_BUF]

    int tid = threadIdx.x, lane = tid & 31, wid = tid >> 5;
    int wm = wid & 1, wn = wid >> 1;                  // 2 x 4 warp grid, warp tile 64x32
    long bm = (long)blockIdx.y * 128, bn = (long)blockIdx.x * 128;

    float acc[4][4][4];
    #pragma unroll
    for (int i = 0; i < 4; i++)
        #pragma unroll
        for (int j = 0; j < 4; j++)
            #pragma unroll
            for (int q = 0; q < 4; q++) acc[i][j][q] = 0.f;

    int nk = K >> 5;

    int ar = tid >> 3, ac = tid & 7;          // A: 128 rows x 8 quads, 4 iters stride 32 rows
    int br = tid >> 5, bc = tid & 31;         // B: 32 rows x 32 quads, 4 iters stride 8 rows

    // prologue: stage 0
    {
        float* a = As; float* b = Bs;
        #pragma unroll
        for (int it = 0; it < 4; it++)
            cpasync16(a + (ar + it * 32) * AS_STRIDE + ac * 4,
                      Ag + (bm + ar + it * 32) * (long)K + ac * 4);
        #pragma unroll
        for (int it = 0; it < 4; it++)
            cpasync16(b + (br + it * 8) * BS_STRIDE + bc * 4,
                      Bg + ((long)(br + it * 8)) * (long)N + bn + bc * 4);
        asm volatile("cp.async.commit_group;\n");
    }

    for (int kt = 0; kt < nk; kt++) {
        int buf = kt & 1;
        if (kt + 1 < nk) {
            float* a = As + (buf ^ 1) * AS_BUF;
            float* b = Bs + (buf ^ 1) * BS_BUF;
            int k1 = kt + 1;
            #pragma unroll
            for (int it = 0; it < 4; it++)
                cpasync16(a + (ar + it * 32) * AS_STRIDE + ac * 4,
                          Ag + (bm + ar + it * 32) * (long)K + k1 * 32 + ac * 4);
            #pragma unroll
            for (int it = 0; it < 4; it++)
                cpasync16(b + (br + it * 8) * BS_STRIDE + bc * 4,
                          Bg + ((long)k1 * 32 + br + it * 8) * (long)N + bn + bc * 4);
            asm volatile("cp.async.commit_group;\n");
            asm volatile("cp.async.wait_group 1;\n");
        } else {
            asm volatile("cp.async.wait_group 0;\n");
        }
        __syncthreads();

        const float* a = As + buf * AS_BUF;
        const float* b = Bs + buf * BS_BUF;

        #pragma unroll
        for (int kk = 0; kk < 32; kk += 8) {
            uint32_t af[4][4], bf[4][2];
            #pragma unroll
            for (int fm = 0; fm < 4; fm++) {
                int row = wm * 64 + fm * 16 + (lane >> 2);
                int col = kk + (lane & 3);
                af[fm][0] = __float_as_uint(a[row * AS_STRIDE + col]);
                af[fm][1] = __float_as_uint(a[(row + 8) * AS_STRIDE + col]);
                af[fm][2] = __float_as_uint(a[row * AS_STRIDE + col + 4]);
                af[fm][3] = __float_as_uint(a[(row + 8) * AS_STRIDE + col + 4]);
            }
            #pragma unroll
            for (int fn = 0; fn < 4; fn++) {
                int cn = wn * 32 + fn * 8 + (lane >> 2);
                int rk = kk + (lane & 3);
                bf[fn][0] = __float_as_uint(b[rk * BS_STRIDE + cn]);
                bf[fn][1] = __float_as_uint(b[(rk + 4) * BS_STRIDE + cn]);
            }
            #pragma unroll
            for (int fm = 0; fm < 4; fm++)
                #pragma unroll
                for (int fn = 0; fn < 4; fn++)
                    mma_tf32(acc[fm][fn], af[fm], bf[fn]);
        }
        __syncthreads();
    }

    #pragma unroll
    for (int fm = 0; fm < 4; fm++) {
        long row = bm + wm * 64 + fm * 16 + (lane >> 2);
        #pragma unroll
        for (int fn = 0; fn < 4; fn++) {
            long col = bn + wn * 32 + fn * 8 + (lane & 3) * 2;
            *(float2*)&C[row * N + col]       = make_float2(acc[fm][fn][0], acc[fm][fn][1]);
            *(float2*)&C[(row + 8) * N + col] = make_float2(acc[fm][fn][2], acc[fm][fn][3]);
        }
    }
}

// ---------------- fused scores + online softmax + A accumulation ------------
// One block per segment. x chunk cached in smem; single pass over x (512 MB).
__global__ __launch_bounds__(256) void k_fused(const float* __restrict__ x) {
    __shared__ __align__(16) float g_sh[2048];        // G row for this segment
    __shared__ __align__(16) float x_sh[32 * 256];    // chunk of x rows
    __shared__ __align__(16) float sc_sh[32 * 8];     // per-row per-head exp weights
    __shared__ float f_sh[8];                         // rescale factors
    __shared__ float den_sh[8];

    int s = blockIdx.x;
    int tid = threadIdx.x, lane = tid & 31, w = tid >> 5;
    int b = d_start[s], e = d_start[s + 1];

    // load G row (2048 floats)
    {
        const float4* gp = (const float4*)(d_G + (size_t)s * 2048);
        float4* gs = (float4*)g_sh;
        gs[tid] = gp[tid];
        gs[tid + 256] = gp[tid + 256];
    }

    float a0 = 0, a1 = 0, a2 = 0, a3 = 0, a4 = 0, a5 = 0, a6 = 0, a7 = 0; // A[d=tid, h]
    float m_run = -3.4e38f, den_run = 0.f;            // per-warp (warp w = head w)
    const float scale = 0.17677669529663687f;         // 1/sqrt(32)

    for (int c0 = b; c0 < e; c0 += 32) {
        int m = min(32, e - c0);
        __syncthreads();  // prior reads of x_sh / sc_sh done
        {
            const float4* xg = (const float4*)(x + (size_t)c0 * 256);
            float4* xs = (float4*)x_sh;
            for (int i = tid; i < m * 64; i += 256) xs[i] = xg[i];
        }
        __syncthreads();

        // scores: warp w takes rows i = w, w+8, ...
        for (int i = w; i < m; i += 8) {
            const float* xr = x_sh + i * 256;
            float p0 = 0, p1 = 0, p2 = 0, p3 = 0, p4 = 0, p5 = 0, p6 = 0, p7 = 0;
            #pragma unroll
            for (int dd = 0; dd < 8; dd++) {
                int d = lane + dd * 32;
                float xv = xr[d];
                float4 g0 = *(const float4*)&g_sh[d * 8];
                float4 g1 = *(const float4*)&g_sh[d * 8 + 4];
                p0 += xv * g0.x; p1 += xv * g0.y; p2 += xv * g0.z; p3 += xv * g0.w;
                p4 += xv * g1.x; p5 += xv * g1.y; p6 += xv * g1.z; p7 += xv * g1.w;
            }
            #pragma unroll
            for (int off = 16; off; off >>= 1) {
                p0 += __shfl_xor_sync(0xffffffffu, p0, off);
                p1 += __shfl_xor_sync(0xffffffffu, p1, off);
                p2 += __shfl_xor_sync(0xffffffffu, p2, off);
                p3 += __shfl_xor_sync(0xffffffffu, p3, off);
                p4 += __shfl_xor_sync(0xffffffffu, p4, off);
                p5 += __shfl_xor_sync(0xffffffffu, p5, off);
                p6 += __shfl_xor_sync(0xffffffffu, p6, off);
                p7 += __shfl_xor_sync(0xffffffffu, p7, off);
            }
            if (lane == 0) {
                *(float4*)&sc_sh[i * 8]     = make_float4(p0 * scale, p1 * scale, p2 * scale, p3 * scale);
                *(float4*)&sc_sh[i * 8 + 4] = make_float4(p4 * scale, p5 * scale, p6 * scale, p7 * scale);
            }
        }
        __syncthreads();

        // online softmax update: warp w owns head w
        {
            float sc = (lane < m) ? sc_sh[lane * 8 + w] : -3.4e38f;
            float cmax = sc;
            #pragma unroll
            for (int off = 16; off; off >>= 1)
                cmax = fmaxf(cmax, __shfl_xor_sync(0xffffffffu, cmax, off));
            float nm = fmaxf(m_run, cmax);
            float f = __expf(m_run - nm);
            float ev = (lane < m) ? __expf(sc - nm) : 0.f;
            if (lane < m) sc_sh[lane * 8 + w] = ev;
            float csum = ev;
            #pragma unroll
            for (int off = 16; off; off >>= 1)
                csum += __shfl_xor_sync(0xffffffffu, csum, off);
            den_run = den_run * f + csum;
            m_run = nm;
            if (lane == 0) f_sh[w] = f;
        }
        __syncthreads();

        // accumulate A: thread tid owns d = tid, all 8 heads
        {
            float f0 = f_sh[0], f1 = f_sh[1], f2 = f_sh[2], f3 = f_sh[3];
            float f4 = f_sh[4], f5 = f_sh[5], f6 = f_sh[6], f7 = f_sh[7];
            a0 *= f0; a1 *= f1; a2 *= f2; a3 *= f3;
            a4 *= f4; a5 *= f5; a6 *= f6; a7 *= f7;
            for (int i = 0; i < m; i++) {
                float xv = x_sh[i * 256 + tid];
                float4 e0 = *(const float4*)&sc_sh[i * 8];
                float4 e1 = *(const float4*)&sc_sh[i * 8 + 4];
                a0 += e0.x * xv; a1 += e0.y * xv; a2 += e0.z * xv; a3 += e0.w * xv;
                a4 += e1.x * xv; a5 += e1.y * xv; a6 += e1.z * xv; a7 += e1.w * xv;
            }
        }
    }

    // publish denominators
    if (lane == 0) den_sh[w] = den_run;
    __syncthreads();

    float r0 = den_sh[0] > 0.f ? 1.f / den_sh[0] : 0.f;
    float r1 = den_sh[1] > 0.f ? 1.f / den_sh[1] : 0.f;
    float r2 = den_sh[2] > 0.f ? 1.f / den_sh[2] : 0.f;
    float r3 = den_sh[3] > 0.f ? 1.f / den_sh[3] : 0.f;
    float r4 = den_sh[4] > 0.f ? 1.f / den_sh[4] : 0.f;
    float r5 = den_sh[5] > 0.f ? 1.f / den_sh[5] : 0.f;
    float r6 = den_sh[6] > 0.f ? 1.f / den_sh[6] : 0.f;
    float r7 = den_sh[7] > 0.f ? 1.f / den_sh[7] : 0.f;

    float* ap = d_A + (size_t)s * 2048 + tid * 8;
    *(float4*)ap = make_float4(tfround(a0 * r0), tfround(a1 * r1),
                               tfround(a2 * r2), tfround(a3 * r3));
    *(float4*)(ap + 4) = make_float4(tfround(a4 * r4), tfround(a5 * r5),
                                     tfround(a6 * r6), tfround(a7 * r7));
}

// ---------------- launch ----------------------------------------------------
extern "C" void kernel_launch(void* const* d_in, const int* in_sizes, int n_in,
                              void* d_out, int out_size) {
    const float* x   = (const float*)d_in[0];
    const int*   seg = (const int*)d_in[1];
    int wb = n_in - 4;                      // weights are the last 4 inputs
    const float* Wq = (const float*)d_in[wb + 0];
    const float* Wk = (const float*)d_in[wb + 1];
    const float* Wv = (const float*)d_in[wb + 2];
    const float* Wo = (const float*)d_in[wb + 3];
    float* out = (float*)d_out;

    int N = in_sizes[0] / 256;
    const int S = S_FIX;

    cudaFuncSetAttribute(k_gemm, cudaFuncAttributeMaxDynamicSharedMemorySize, GEMM_SMEM);

    k_bounds<<<(S + 1 + 255) / 256, 256>>>(seg, N, S);
    k_prep<<<2048, 256>>>(Wq, Wk, Wv, Wo);
    k_pool<<<S, 256>>>(x);
    k_gemm<<<dim3(2048 / 128, S / 128), 256, GEMM_SMEM>>>(0, nullptr, S, 2048, 256);  // G = mean @ Bbig
    k_fused<<<S, 256>>>(x);
    k_gemm<<<dim3(256 / 128, S / 128), 256, GEMM_SMEM>>>(1, out, S, 256, 2048);       // out = A @ Mstack
}